// round 1
// baseline (speedup 1.0000x reference)
#include <cuda_runtime.h>
#include <cuda_bf16.h>
#include <math.h>

// Problem dims
#define TT 512
#define BB 64
#define II 512
#define HH 512

// ---------------- device scratch (no allocations allowed) ----------------
// h double buffer, packed per batch-group: g_h[buf][group][k] = float4 of 4 batches
__device__ float4 g_h[2][16][512];
__device__ float  g_xz[TT * BB];   // [t][b]  (includes zt_w_b)
__device__ float  g_xr[TT * BB];   // [t][b]  (includes rt_w_b)

// ---------------- kernel 0: init hidden into packed layout ----------------
__global__ void init_h_kernel(const float* __restrict__ hidden) {
    int i = blockIdx.x * 256 + threadIdx.x;           // 0 .. 32767
    if (i >= BB * HH) return;
    int b = i >> 9;
    int k = i & 511;
    float* dst = (float*)&g_h[0][b >> 2][k];
    dst[b & 3] = hidden[i];
}

// ---------------- kernel 1: gate input projections xz, xr ----------------
// one warp per (t,b) row; both gates fused
__global__ void gate_pre_kernel(const float* __restrict__ in,
                                const float* __restrict__ zw, const float* __restrict__ zb,
                                const float* __restrict__ rw, const float* __restrict__ rb) {
    int row  = blockIdx.x * 8 + (threadIdx.x >> 5);   // 0 .. 32767
    int lane = threadIdx.x & 31;
    const float4* a4 = (const float4*)(in + (size_t)row * II);
    const float4* z4 = (const float4*)zw;
    const float4* r4 = (const float4*)rw;
    float az = 0.f, ar = 0.f;
#pragma unroll 4
    for (int i = lane; i < II / 4; i += 32) {
        float4 v = a4[i];
        float4 z = z4[i];
        float4 r = r4[i];
        az += v.x * z.x + v.y * z.y + v.z * z.z + v.w * z.w;
        ar += v.x * r.x + v.y * r.y + v.z * r.z + v.w * r.w;
    }
#pragma unroll
    for (int off = 16; off >= 1; off >>= 1) {
        az += __shfl_xor_sync(0xffffffffu, az, off);
        ar += __shfl_xor_sync(0xffffffffu, ar, off);
    }
    if (lane == 0) {
        g_xz[row] = az + zb[0];
        g_xr[row] = ar + rb[0];
    }
}

// ---------------- kernel 2: xn GEMM  C[m][n] = sum_k A[m][k]*W[n][k] + bias[n] ----
// M = T*B = 32768, N = 512, K = 512. Written into d_out (overwritten later by scan).
#define GM_BM 128
#define GM_BN 64
#define GM_BK 16
__global__ __launch_bounds__(256) void xn_gemm_kernel(const float* __restrict__ A,
                                                      const float* __restrict__ W,
                                                      const float* __restrict__ bias,
                                                      float* __restrict__ C) {
    __shared__ float As[GM_BK][GM_BM];
    __shared__ float Ws[GM_BK][GM_BN];

    int bm = blockIdx.x * GM_BM;
    int bn = blockIdx.y * GM_BN;
    int tid = threadIdx.x;
    int tcol = tid & 15;    // 16 cols * TN=4  -> 64
    int trow = tid >> 4;    // 16 rows * TM=8  -> 128

    float acc[8][4];
#pragma unroll
    for (int i = 0; i < 8; i++)
#pragma unroll
        for (int j = 0; j < 4; j++) acc[i][j] = 0.f;

    const float4* A4 = (const float4*)A;
    const float4* W4 = (const float4*)W;

    for (int k0 = 0; k0 < II; k0 += GM_BK) {
        // load A tile: 128 rows x 16 k = 512 float4 slots, 2 per thread
#pragma unroll
        for (int q = 0; q < 2; q++) {
            int s  = tid + q * 256;
            int m  = s >> 2;
            int kq = s & 3;
            float4 v = A4[(size_t)(bm + m) * (II / 4) + (k0 >> 2) + kq];
            As[kq * 4 + 0][m] = v.x;
            As[kq * 4 + 1][m] = v.y;
            As[kq * 4 + 2][m] = v.z;
            As[kq * 4 + 3][m] = v.w;
        }
        // load W tile: 64 rows x 16 k = 256 float4 slots, 1 per thread
        {
            int s  = tid;
            int n  = s >> 2;
            int kq = s & 3;
            float4 v = W4[(size_t)(bn + n) * (II / 4) + (k0 >> 2) + kq];
            Ws[kq * 4 + 0][n] = v.x;
            Ws[kq * 4 + 1][n] = v.y;
            Ws[kq * 4 + 2][n] = v.z;
            Ws[kq * 4 + 3][n] = v.w;
        }
        __syncthreads();
#pragma unroll
        for (int kk = 0; kk < GM_BK; kk++) {
            float4 a01 = *(const float4*)&As[kk][trow * 8];
            float4 a23 = *(const float4*)&As[kk][trow * 8 + 4];
            float4 wv  = *(const float4*)&Ws[kk][tcol * 4];
            float af[8] = {a01.x, a01.y, a01.z, a01.w, a23.x, a23.y, a23.z, a23.w};
            float wf[4] = {wv.x, wv.y, wv.z, wv.w};
#pragma unroll
            for (int i = 0; i < 8; i++)
#pragma unroll
                for (int j = 0; j < 4; j++) acc[i][j] = fmaf(af[i], wf[j], acc[i][j]);
        }
        __syncthreads();
    }

    float4 bv = ((const float4*)bias)[(bn >> 2) + tcol];
#pragma unroll
    for (int i = 0; i < 8; i++) {
        int m = bm + trow * 8 + i;
        float4 o;
        o.x = acc[i][0] + bv.x;
        o.y = acc[i][1] + bv.y;
        o.z = acc[i][2] + bv.z;
        o.w = acc[i][3] + bv.w;
        ((float4*)C)[(size_t)m * (HH / 4) + (bn >> 2) + tcol] = o;
    }
}

// ---------------- kernel 3: recurrent scan ----------------
// Grid 128 CTAs, cluster of 8 along x. Cluster g handles batches 4g..4g+3.
// CTA rank r handles h outputs [64r, 64r+64). Weight slice (transposed) cached in smem.
// h exchanged through g_h double buffer + barrier.cluster per step.
#define SC_SMEM (131072 + 8192 + 4096 + 2048 + 2048 + 256 + 32)

extern __shared__ char sc_smem[];

__global__ void __cluster_dims__(8, 1, 1) __launch_bounds__(256, 1)
scan_kernel(const float* __restrict__ ztu_g, const float* __restrict__ ztub,
            const float* __restrict__ rtu_g, const float* __restrict__ rtub,
            const float* __restrict__ huw, const float* __restrict__ hub_g,
            float* __restrict__ out, int tail) {
    float*  wT   = (float*)sc_smem;                      // [512][64]
    float4* h4   = (float4*)(sc_smem + 131072);          // [512]
    float4* part = (float4*)(sc_smem + 131072 + 8192);   // [4][64]
    float*  ztu  = (float*)(sc_smem + 143360);           // [512]
    float*  rtu  = (float*)(sc_smem + 145408);           // [512]
    float*  hub  = (float*)(sc_smem + 147456);           // [64]
    float*  zr   = (float*)(sc_smem + 147712);           // zt[4], rt[4]

    int tid    = threadIdx.x;
    int rank   = blockIdx.x & 7;
    int grp    = blockIdx.x >> 3;
    int jjbase = rank * 64;

    // one-time: cache transposed weight slice + gate weights
    for (int i = tid; i < 64 * 512; i += 256) {
        int jj = i >> 9;
        int k  = i & 511;
        wT[k * 64 + jj] = huw[(size_t)(jjbase + jj) * HH + k];
    }
    for (int i = tid; i < 512; i += 256) {
        ztu[i] = ztu_g[i];
        rtu[i] = rtu_g[i];
    }
    if (tid < 64) hub[tid] = hub_g[jjbase + tid];
    __syncthreads();

    float zub = ztub[0], rub = rtub[0];
    int jj   = tid & 63;
    int kseg = tid >> 6;
    int k0   = kseg * 128;

    for (int t = 0; t < TT; t++) {
        int p = t & 1;
        // phase 1: load current h (all 512, packed 4 batches)
        for (int i = tid; i < 512; i += 256) h4[i] = g_h[p][grp][i];
        __syncthreads();

        // phase 2: gate pre-activations (8 warps: warp -> (batch=w>>1, gate=w&1))
        {
            int warp = tid >> 5, lane = tid & 31;
            int b = warp >> 1;
            const float* uw = (warp & 1) ? rtu : ztu;
            float acc = 0.f;
#pragma unroll 4
            for (int k = lane; k < 512; k += 32) {
                float hv = ((const float*)&h4[k])[b];
                acc = fmaf(hv, uw[k], acc);
            }
#pragma unroll
            for (int off = 16; off >= 1; off >>= 1)
                acc += __shfl_xor_sync(0xffffffffu, acc, off);
            if (lane == 0) {
                float x;
                if (warp & 1) x = g_xr[t * BB + grp * 4 + b] + rub;
                else          x = g_xz[t * BB + grp * 4 + b] + zub;
                float v = acc + x;
                zr[(warp & 1) * 4 + b] = 1.f / (1.f + expf(-v));
            }
        }

        // phase 3: main recurrent dot, K split across 4 segments
        {
            float a0 = 0.f, a1 = 0.f, a2 = 0.f, a3 = 0.f;
#pragma unroll 4
            for (int k = k0; k < k0 + 128; k++) {
                float w  = wT[k * 64 + jj];
                float4 hv = h4[k];
                a0 = fmaf(hv.x, w, a0);
                a1 = fmaf(hv.y, w, a1);
                a2 = fmaf(hv.z, w, a2);
                a3 = fmaf(hv.w, w, a3);
            }
            part[kseg * 64 + jj] = make_float4(a0, a1, a2, a3);
        }
        __syncthreads();

        // phase 4: finish — thread (b = tid>>6, jj) combines, applies gates, writes h_new
        {
            int b = tid >> 6;
            const float* pp = (const float*)part;
            float s = pp[(0 * 64 + jj) * 4 + b] + pp[(1 * 64 + jj) * 4 + b] +
                      pp[(2 * 64 + jj) * 4 + b] + pp[(3 * 64 + jj) * 4 + b];
            float ztv = zr[b];
            float rtv = zr[4 + b];
            int   hidx = jjbase + jj;
            size_t base = (size_t)t * BB * HH + (size_t)(grp * 4 + b) * HH + hidx;
            float xn = out[base];               // precomputed xn (includes h_w_b)
            float av = s + hub[jj];
            float nt = tanhf(fmaf(av, rtv, xn));
            float hold = ((const float*)&h4[hidx])[b];
            float hn = (1.f - ztv) * nt + ztv * hold;
            out[base] = hn;
            ((float*)&g_h[1 - p][grp][hidx])[b] = hn;
            if (t == TT - 1 && tail >= BB * HH) {
                out[(size_t)TT * BB * HH + (size_t)(grp * 4 + b) * HH + hidx] = hn;
            }
        }

        // cluster barrier: all 8 CTAs' h_new chunks visible before next step
        asm volatile("barrier.cluster.arrive.release.aligned;" ::: "memory");
        asm volatile("barrier.cluster.wait.acquire.aligned;" ::: "memory");
        __syncthreads();  // protect smem (h4/part/zr) reuse across iterations
    }
}

// ---------------- launch ----------------
extern "C" void kernel_launch(void* const* d_in, const int* in_sizes, int n_in,
                              void* d_out, int out_size) {
    const float* input  = (const float*)d_in[0];
    const float* hidden = (const float*)d_in[1];
    const float* zt_w_w = (const float*)d_in[2];
    const float* zt_w_b = (const float*)d_in[3];
    const float* zt_u_w = (const float*)d_in[4];
    const float* zt_u_b = (const float*)d_in[5];
    const float* rt_w_w = (const float*)d_in[6];
    const float* rt_w_b = (const float*)d_in[7];
    const float* rt_u_w = (const float*)d_in[8];
    const float* rt_u_b = (const float*)d_in[9];
    const float* h_w_w  = (const float*)d_in[10];
    const float* h_w_b  = (const float*)d_in[11];
    const float* h_u_w  = (const float*)d_in[12];
    const float* h_u_b  = (const float*)d_in[13];
    float* out = (float*)d_out;

    int tail = out_size - TT * BB * HH;

    // 0) init packed hidden
    init_h_kernel<<<(BB * HH + 255) / 256, 256>>>(hidden);

    // 1) gate input projections
    gate_pre_kernel<<<TT * BB / 8, 256>>>(input, zt_w_w, zt_w_b, rt_w_w, rt_w_b);

    // 2) xn GEMM into d_out
    {
        dim3 grid(TT * BB / GM_BM, HH / GM_BN);
        xn_gemm_kernel<<<grid, 256>>>(input, h_w_w, h_w_b, out);
    }

    // 3) recurrent scan (16 clusters of 8 CTAs)
    static int smem_set = 0;
    if (!smem_set) {
        cudaFuncSetAttribute(scan_kernel, cudaFuncAttributeMaxDynamicSharedMemorySize, SC_SMEM);
        smem_set = 1;
    }
    scan_kernel<<<128, 256, SC_SMEM>>>(zt_u_w, zt_u_b, rt_u_w, rt_u_b, h_u_w, h_u_b,
                                       out, tail);
}

// round 3
// speedup vs baseline: 1.3326x; 1.3326x over previous
#include <cuda_runtime.h>
#include <cuda_bf16.h>
#include <math.h>

// Problem dims
#define TT 512
#define BB 64
#define II 512
#define HH 512

// ---------------- device scratch ----------------
__device__ float g_xz[TT * BB];   // [t][b] includes zt_w_b
__device__ float g_xr[TT * BB];   // [t][b] includes rt_w_b

// ---------------- f32x2 helpers ----------------
typedef unsigned long long ull;
union F4U { float4 f; ull u[2]; };
union U64F2 { ull u; float2 f; };

__device__ __forceinline__ void fma2(ull& d, ull a, ull b) {
    asm("fma.rn.f32x2 %0, %1, %2, %0;" : "+l"(d) : "l"(a), "l"(b));
}
__device__ __forceinline__ ull dup2(float x) {
    ull r; asm("mov.b64 %0, {%1, %1};" : "=l"(r) : "f"(x)); return r;
}

// ---------------- kernel 1: gate input projections xz, xr ----------------
__global__ void gate_pre_kernel(const float* __restrict__ in,
                                const float* __restrict__ zw, const float* __restrict__ zb,
                                const float* __restrict__ rw, const float* __restrict__ rb) {
    int row  = blockIdx.x * 8 + (threadIdx.x >> 5);
    int lane = threadIdx.x & 31;
    const float4* a4 = (const float4*)(in + (size_t)row * II);
    const float4* z4 = (const float4*)zw;
    const float4* r4 = (const float4*)rw;
    float az = 0.f, ar = 0.f;
#pragma unroll 4
    for (int i = lane; i < II / 4; i += 32) {
        float4 v = a4[i];
        float4 z = z4[i];
        float4 r = r4[i];
        az += v.x * z.x + v.y * z.y + v.z * z.z + v.w * z.w;
        ar += v.x * r.x + v.y * r.y + v.z * r.z + v.w * r.w;
    }
#pragma unroll
    for (int off = 16; off >= 1; off >>= 1) {
        az += __shfl_xor_sync(0xffffffffu, az, off);
        ar += __shfl_xor_sync(0xffffffffu, ar, off);
    }
    if (lane == 0) {
        g_xz[row] = az + zb[0];
        g_xr[row] = ar + rb[0];
    }
}

// ---------------- kernel 2: xn GEMM (f32x2) ----------------
#define GM_BM 128
#define GM_BN 64
#define GM_BK 16
__global__ __launch_bounds__(256) void xn_gemm_kernel(const float* __restrict__ A,
                                                      const float* __restrict__ W,
                                                      const float* __restrict__ bias,
                                                      float* __restrict__ C) {
    __shared__ float As[GM_BK][GM_BM];
    __shared__ float Ws[GM_BK][GM_BN];

    int bm = blockIdx.x * GM_BM;
    int bn = blockIdx.y * GM_BN;
    int tid = threadIdx.x;
    int tcol = tid & 15;
    int trow = tid >> 4;

    ull acc2[4][4];   // [m-pair][n], each = {row 2mp, row 2mp+1}
#pragma unroll
    for (int i = 0; i < 4; i++)
#pragma unroll
        for (int j = 0; j < 4; j++) acc2[i][j] = 0ull;

    const float4* A4 = (const float4*)A;
    const float4* W4 = (const float4*)W;

    for (int k0 = 0; k0 < II; k0 += GM_BK) {
#pragma unroll
        for (int q = 0; q < 2; q++) {
            int s  = tid + q * 256;
            int m  = s >> 2;
            int kq = s & 3;
            float4 v = A4[(size_t)(bm + m) * (II / 4) + (k0 >> 2) + kq];
            As[kq * 4 + 0][m] = v.x;
            As[kq * 4 + 1][m] = v.y;
            As[kq * 4 + 2][m] = v.z;
            As[kq * 4 + 3][m] = v.w;
        }
        {
            int s  = tid;
            int n  = s >> 2;
            int kq = s & 3;
            float4 v = W4[(size_t)(bn + n) * (II / 4) + (k0 >> 2) + kq];
            Ws[kq * 4 + 0][n] = v.x;
            Ws[kq * 4 + 1][n] = v.y;
            Ws[kq * 4 + 2][n] = v.z;
            Ws[kq * 4 + 3][n] = v.w;
        }
        __syncthreads();
#pragma unroll
        for (int kk = 0; kk < GM_BK; kk++) {
            F4U a01, a23, wv;
            a01.f = *(const float4*)&As[kk][trow * 8];
            a23.f = *(const float4*)&As[kk][trow * 8 + 4];
            wv.f  = *(const float4*)&Ws[kk][tcol * 4];
            ull ap[4] = {a01.u[0], a01.u[1], a23.u[0], a23.u[1]};
            ull wd[4] = {dup2(wv.f.x), dup2(wv.f.y), dup2(wv.f.z), dup2(wv.f.w)};
#pragma unroll
            for (int i = 0; i < 4; i++)
#pragma unroll
                for (int j = 0; j < 4; j++) fma2(acc2[i][j], ap[i], wd[j]);
        }
        __syncthreads();
    }

    float4 bv = ((const float4*)bias)[(bn >> 2) + tcol];
#pragma unroll
    for (int i = 0; i < 8; i++) {
        int mp = i >> 1, h = i & 1;
        int m = bm + trow * 8 + i;
        float4 o;
        U64F2 c0, c1, c2, c3;
        c0.u = acc2[mp][0]; c1.u = acc2[mp][1]; c2.u = acc2[mp][2]; c3.u = acc2[mp][3];
        o.x = (h ? c0.f.y : c0.f.x) + bv.x;
        o.y = (h ? c1.f.y : c1.f.x) + bv.y;
        o.z = (h ? c2.f.y : c2.f.x) + bv.z;
        o.w = (h ? c3.f.y : c3.f.x) + bv.w;
        ((float4*)C)[(size_t)m * (HH / 4) + (bn >> 2) + tcol] = o;
    }
}

// ---------------- kernel 3: recurrent scan ----------------
// 16 clusters x 8 CTAs, 512 threads/CTA. Cluster g -> batches 4g..4g+3.
// CTA rank r -> h outputs [64r,64r+64). h exchanged via DSMEM fan-out +
// one cluster barrier per step. Weights cached transposed (float2 jj-pairs).
#define WT_OFF   0                       // float2[512][32] = 131072
#define HB_OFF   131072                  // float4[2][512]  = 16384
#define PART_OFF (HB_OFF + 16384)        // float[16][256]  = 16384
#define ZRP_OFF  (PART_OFF + 16384)      // float4[16]      = 256
#define GW_OFF   (ZRP_OFF + 256)         // ztu[512]+rtu[512] = 4096
#define HUB_OFF  (GW_OFF + 4096)         // float[64] = 256
#define HST_OFF  (HUB_OFF + 256)         // float[256] staging = 1024
#define SC_SMEM  (HST_OFF + 1024)

extern __shared__ char sc_smem[];

__device__ __forceinline__ unsigned smem_u32(const void* p) {
    return (unsigned)__cvta_generic_to_shared(p);
}

__global__ void __cluster_dims__(8, 1, 1) __launch_bounds__(512, 1)
scan_kernel(const float* __restrict__ hidden,
            const float* __restrict__ ztu_g, const float* __restrict__ ztub,
            const float* __restrict__ rtu_g, const float* __restrict__ rtub,
            const float* __restrict__ huw, const float* __restrict__ hub_g,
            float* __restrict__ out, int tail) {
    float2* wT2  = (float2*)(sc_smem + WT_OFF);
    float4* hb4  = (float4*)(sc_smem + HB_OFF);     // [2][512]
    float*  part = (float*)(sc_smem + PART_OFF);    // [ks][b][jj]
    float*  zrpf = (float*)(sc_smem + ZRP_OFF);     // float4[gate*8+ks8]
    float*  ztu  = (float*)(sc_smem + GW_OFF);
    float*  rtu  = (float*)(sc_smem + GW_OFF + 2048);
    float*  hub  = (float*)(sc_smem + HUB_OFF);
    float*  hst  = (float*)(sc_smem + HST_OFF);     // [jj*4+b]

    int tid    = threadIdx.x;
    int rank   = blockIdx.x & 7;
    int grp    = blockIdx.x >> 3;
    int jjbase = rank * 64;

    // -------- prologue: weights + initial h into smem --------
    for (int i = tid; i < 64 * 512; i += 512) {
        int jj = i >> 9, k = i & 511;
        float w = huw[(size_t)(jjbase + jj) * HH + k];
        ((float*)wT2)[(k * 32 + (jj >> 1)) * 2 + (jj & 1)] = w;
    }
    for (int i = tid; i < 512; i += 512) { ztu[i] = ztu_g[i]; rtu[i] = rtu_g[i]; }
    for (int i = tid + 512; i < 1024; i += 512) { /* nop */ }
    for (int i = tid; i < 512; i += 512) { }  // (loops above cover 512 each)
    // full coverage for gate weights (512 threads, 512 elems: one each)
    // initial hidden: pack 4 batches
    for (int i = tid; i < 4 * 512; i += 512) {
        int b = i >> 9, k = i & 511;
        ((float*)hb4)[k * 4 + b] = hidden[(size_t)(grp * 4 + b) * HH + k];
    }
    if (tid < 64) hub[tid] = hub_g[jjbase + tid];
    float zub = ztub[0], rub = rtub[0];
    __syncthreads();

    int lane = tid & 31;
    int warp = tid >> 5;
    int jjp  = lane;          // 0..31 (jj pair index)
    int ks   = warp;          // 0..15 (k segment, 32 k each)
    int gate = warp & 1;
    int ks8  = warp >> 1;
    int jj4  = tid & 63;
    int b4   = (tid >> 6) & 3;

    for (int t = 0; t < TT; t++) {
        int s = t & 1;
        const float4* hb = hb4 + s * 512;

        // -------- early global prefetch (independent of h) --------
        size_t obase = (size_t)t * BB * HH + (size_t)(grp * 4 + b4) * HH + jjbase + jj4;
        float xnv = out[obase];
        float xzv = g_xz[t * BB + grp * 4 + b4];
        float xrv = g_xr[t * BB + grp * 4 + b4];

        // -------- gates: 16 warps = gate(2) x ks8(8), 64 k each --------
        {
            const float* uw = gate ? rtu : ztu;
            float4 g = make_float4(0.f, 0.f, 0.f, 0.f);
#pragma unroll
            for (int it = 0; it < 2; it++) {
                int k = ks8 * 64 + it * 32 + lane;
                float4 hv = hb[k];
                float  u  = uw[k];
                g.x = fmaf(hv.x, u, g.x);
                g.y = fmaf(hv.y, u, g.y);
                g.z = fmaf(hv.z, u, g.z);
                g.w = fmaf(hv.w, u, g.w);
            }
#pragma unroll
            for (int off = 16; off >= 1; off >>= 1) {
                g.x += __shfl_xor_sync(0xffffffffu, g.x, off);
                g.y += __shfl_xor_sync(0xffffffffu, g.y, off);
                g.z += __shfl_xor_sync(0xffffffffu, g.z, off);
                g.w += __shfl_xor_sync(0xffffffffu, g.w, off);
            }
            if (lane == 0) ((float4*)zrpf)[gate * 8 + ks8] = g;
        }

        // -------- phase 3: main dot, f32x2, 2 jj x 4 b per thread --------
        {
            const float2* wrow = wT2 + ks * 32 * 32 + jjp;
            const float4* hrow = hb + ks * 32;
            ull a00 = 0, a01v = 0, a10 = 0, a11v = 0;
#pragma unroll 8
            for (int kk = 0; kk < 32; kk++) {
                float2 w2 = wrow[(size_t)kk * 32];
                F4U hv; hv.f = hrow[kk];
                ull wp0 = dup2(w2.x);
                ull wp1 = dup2(w2.y);
                fma2(a00,  hv.u[0], wp0);
                fma2(a01v, hv.u[1], wp0);
                fma2(a10,  hv.u[0], wp1);
                fma2(a11v, hv.u[1], wp1);
            }
            U64F2 c00, c01, c10, c11;
            c00.u = a00; c01.u = a01v; c10.u = a10; c11.u = a11v;
            float* pp = part + ks * 256;
            ((float2*)(pp + 0 * 64))[jjp] = make_float2(c00.f.x, c10.f.x);
            ((float2*)(pp + 1 * 64))[jjp] = make_float2(c00.f.y, c10.f.y);
            ((float2*)(pp + 2 * 64))[jjp] = make_float2(c01.f.x, c11.f.x);
            ((float2*)(pp + 3 * 64))[jjp] = make_float2(c01.f.y, c11.f.y);
        }
        __syncthreads();

        // -------- phase 4: reduce + gates + write --------
        if (tid < 256) {
            float ssum = 0.f;
#pragma unroll
            for (int ki = 0; ki < 16; ki++) ssum += part[ki * 256 + b4 * 64 + jj4];
            float gz = 0.f, gr = 0.f;
#pragma unroll
            for (int k8 = 0; k8 < 8; k8++) {
                gz += zrpf[(0 * 8 + k8) * 4 + b4];
                gr += zrpf[(1 * 8 + k8) * 4 + b4];
            }
            float zt = 1.f / (1.f + expf(-(xzv + gz + zub)));
            float rt = 1.f / (1.f + expf(-(xrv + gr + rub)));
            float av = ssum + hub[jj4];
            float nt = tanhf(fmaf(av, rt, xnv));
            float hold = ((const float*)hb)[(jjbase + jj4) * 4 + b4];
            float hn = (1.f - zt) * nt + zt * hold;
            out[obase] = hn;
            hst[jj4 * 4 + b4] = hn;
            if (t == TT - 1 && tail >= BB * HH) {
                out[(size_t)TT * BB * HH + (size_t)(grp * 4 + b4) * HH + jjbase + jj4] = hn;
            }
        }
        __syncthreads();

        // -------- fan-out: DSMEM stores of our h chunk to all 8 CTAs --------
        if (tid < 64) {
            F4U v; v.f = ((const float4*)hst)[tid];
            unsigned loc = smem_u32(&hb4[(s ^ 1) * 512 + jjbase + tid]);
#pragma unroll
            for (int r = 0; r < 8; r++) {
                unsigned rem;
                asm("mapa.shared::cluster.u32 %0, %1, %2;" : "=r"(rem) : "r"(loc), "r"(r));
                asm volatile("st.shared::cluster.b64 [%0], %1;" :: "r"(rem), "l"(v.u[0]) : "memory");
                asm volatile("st.shared::cluster.b64 [%0+8], %1;" :: "r"(rem), "l"(v.u[1]) : "memory");
            }
        }

        // -------- cluster barrier (release/acquire): h(t+1) visible --------
        asm volatile("barrier.cluster.arrive.release.aligned;" ::: "memory");
        asm volatile("barrier.cluster.wait.acquire.aligned;" ::: "memory");
    }
}

// ---------------- launch ----------------
extern "C" void kernel_launch(void* const* d_in, const int* in_sizes, int n_in,
                              void* d_out, int out_size) {
    const float* input  = (const float*)d_in[0];
    const float* hidden = (const float*)d_in[1];
    const float* zt_w_w = (const float*)d_in[2];
    const float* zt_w_b = (const float*)d_in[3];
    const float* zt_u_w = (const float*)d_in[4];
    const float* zt_u_b = (const float*)d_in[5];
    const float* rt_w_w = (const float*)d_in[6];
    const float* rt_w_b = (const float*)d_in[7];
    const float* rt_u_w = (const float*)d_in[8];
    const float* rt_u_b = (const float*)d_in[9];
    const float* h_w_w  = (const float*)d_in[10];
    const float* h_w_b  = (const float*)d_in[11];
    const float* h_u_w  = (const float*)d_in[12];
    const float* h_u_b  = (const float*)d_in[13];
    float* out = (float*)d_out;

    int tail = out_size - TT * BB * HH;

    // 1) gate input projections
    gate_pre_kernel<<<TT * BB / 8, 256>>>(input, zt_w_w, zt_w_b, rt_w_w, rt_w_b);

    // 2) xn GEMM into d_out
    {
        dim3 grid(TT * BB / GM_BM, HH / GM_BN);
        xn_gemm_kernel<<<grid, 256>>>(input, h_w_w, h_w_b, out);
    }

    // 3) recurrent scan (16 clusters of 8 CTAs, 512 threads)
    static int smem_set = 0;
    if (!smem_set) {
        cudaFuncSetAttribute(scan_kernel, cudaFuncAttributeMaxDynamicSharedMemorySize, SC_SMEM);
        smem_set = 1;
    }
    scan_kernel<<<128, 512, SC_SMEM>>>(hidden, zt_u_w, zt_u_b, rt_u_w, rt_u_b,
                                       h_u_w, h_u_b, out, tail);
}